// round 9
// baseline (speedup 1.0000x reference)
#include <cuda_runtime.h>
#include <cuda_fp16.h>
#include <cstdint>

// ---------------------------------------------------------------------------
// 2-layer GCN: h = relu(GCN(relu(GCN(x, W1, b1)), W2, b2))
// GCNConv: out = D^{-1/2}(A+I)D^{-1/2} X W + b      (edge_index is int32)
//
// R9: gather processes 2 neighbors per warp LDG.128 (half-warp per fp16 row),
//     4 neighbors per unrolled iteration; shfl_xor(16) combine.
// ---------------------------------------------------------------------------

#define MAX_N 50000
#define MAX_E 600000
#define H 128
#define SCAN_T 1024
#define WPAD 136

__device__ float  g_dinv[MAX_N];
__device__ int    g_cnt[MAX_N];
__device__ int    g_off[MAX_N + 1];
__device__ int    g_cursor[MAX_N];
__device__ int    g_csr_src[MAX_E];
__device__ __half g_xw[MAX_N * H];
__device__ float  g_h[MAX_N * H];

// ---------------------------------------------------------------------------
// CSR build
// ---------------------------------------------------------------------------
__global__ void zero_cnt_kernel(int* cnt, int n) {
    int i = blockIdx.x * blockDim.x + threadIdx.x;
    if (i < n) cnt[i] = 0;
}

__global__ void count_kernel(const int* __restrict__ ei, int* cnt, int e) {
    int i = blockIdx.x * blockDim.x + threadIdx.x;
    if (i < e) atomicAdd(&cnt[ei[e + i]], 1);
}

__global__ void __launch_bounds__(SCAN_T) scan_kernel(
    const int* __restrict__ cnt, int* __restrict__ off,
    int* __restrict__ cursor, float* __restrict__ dinv, int n)
{
    __shared__ int part[SCAN_T];
    const int t = threadIdx.x;
    const int chunk = (n + SCAN_T - 1) / SCAN_T;
    const int beg = t * chunk;
    const int end = min(beg + chunk, n);

    int local = 0;
    for (int i = beg; i < end; i++) local += cnt[i];
    part[t] = local;
    __syncthreads();

    for (int s = 1; s < SCAN_T; s <<= 1) {
        int v = (t >= s) ? part[t - s] : 0;
        __syncthreads();
        part[t] += v;
        __syncthreads();
    }

    int run = (t == 0) ? 0 : part[t - 1];
    for (int i = beg; i < end; i++) {
        int c = cnt[i];
        off[i] = run;
        cursor[i] = run;
        dinv[i] = rsqrtf(1.0f + (float)c);
        run += c;
    }
    if (t == SCAN_T - 1) off[n] = run;
}

__global__ void fill_kernel(const int* __restrict__ ei,
                            int* __restrict__ cursor,
                            int* __restrict__ csr_src, int e)
{
    int i = blockIdx.x * blockDim.x + threadIdx.x;
    if (i < e) {
        int s = ei[i];
        int d = ei[e + i];
        int p = atomicAdd(&cursor[d], 1);
        csr_src[p] = s;
    }
}

// ---------------------------------------------------------------------------
// tf32 helpers
// ---------------------------------------------------------------------------
__device__ __forceinline__ uint32_t f2tf32(float f) {
    uint32_t r;
    asm("cvt.rna.tf32.f32 %0, %1;" : "=r"(r) : "f"(f));
    return r;
}

__device__ __forceinline__ void mma_tf32(float* c,
    uint32_t a0, uint32_t a1, uint32_t a2, uint32_t a3,
    uint32_t b0, uint32_t b1)
{
    asm volatile(
        "mma.sync.aligned.m16n8k8.row.col.f32.tf32.tf32.f32 "
        "{%0,%1,%2,%3}, {%4,%5,%6,%7}, {%8,%9}, {%0,%1,%2,%3};"
        : "+f"(c[0]), "+f"(c[1]), "+f"(c[2]), "+f"(c[3])
        : "r"(a0), "r"(a1), "r"(a2), "r"(a3), "r"(b0), "r"(b1));
}

// ---------------------------------------------------------------------------
// GEMM (tensor cores, pipelined): xw(fp16) = A(fp32) @ W(fp32 -> tf32).
// ---------------------------------------------------------------------------
__global__ void __launch_bounds__(256) gemm_tf32_kernel(
    const float* __restrict__ A, const float* __restrict__ W,
    __half* __restrict__ xw, int n)
{
    extern __shared__ float Ws[];   // [128][WPAD]

    const int tid  = threadIdx.x;
    const int lane = tid & 31;
    const int warp = tid >> 5;
    const int g    = lane >> 2;
    const int t4   = lane & 3;
    const int m0   = blockIdx.x * 128 + warp * 16;

    const float4* W4 = reinterpret_cast<const float4*>(W);
#pragma unroll
    for (int i = tid; i < 128 * 32; i += 256) {
        int r = i >> 5, c4 = i & 31;
        float4 v = W4[r * 32 + c4];
        float* dstp = &Ws[r * WPAD + c4 * 4];
        dstp[0] = __uint_as_float(f2tf32(v.x));
        dstp[1] = __uint_as_float(f2tf32(v.y));
        dstp[2] = __uint_as_float(f2tf32(v.z));
        dstp[3] = __uint_as_float(f2tf32(v.w));
    }

    float acc[16][4];
#pragma unroll
    for (int nt = 0; nt < 16; nt++)
#pragma unroll
        for (int c = 0; c < 4; c++) acc[nt][c] = 0.f;

    const int r0 = m0 + g;
    const int r1 = r0 + 8;
    const bool v0 = r0 < n;
    const bool v1 = r1 < n;
    const float* Ar0 = A + (size_t)r0 * H;
    const float* Ar1 = A + (size_t)r1 * H;

    __syncthreads();

    uint32_t a0 = v0 ? f2tf32(Ar0[t4])     : 0u;
    uint32_t a1 = v1 ? f2tf32(Ar1[t4])     : 0u;
    uint32_t a2 = v0 ? f2tf32(Ar0[t4 + 4]) : 0u;
    uint32_t a3 = v1 ? f2tf32(Ar1[t4 + 4]) : 0u;

#pragma unroll
    for (int kc = 0; kc < 16; kc++) {
        uint32_t na0 = 0u, na1 = 0u, na2 = 0u, na3 = 0u;
        if (kc < 15) {
            const int c0 = (kc + 1) * 8 + t4;
            na0 = v0 ? f2tf32(Ar0[c0])     : 0u;
            na1 = v1 ? f2tf32(Ar1[c0])     : 0u;
            na2 = v0 ? f2tf32(Ar0[c0 + 4]) : 0u;
            na3 = v1 ? f2tf32(Ar1[c0 + 4]) : 0u;
        }

        const float* wb0 = &Ws[(kc * 8 + t4) * WPAD];
        const float* wb1 = &Ws[(kc * 8 + t4 + 4) * WPAD];
#pragma unroll
        for (int nt = 0; nt < 16; nt++) {
            uint32_t b0 = __float_as_uint(wb0[nt * 8 + g]);
            uint32_t b1 = __float_as_uint(wb1[nt * 8 + g]);
            mma_tf32(acc[nt], a0, a1, a2, a3, b0, b1);
        }

        a0 = na0; a1 = na1; a2 = na2; a3 = na3;
    }

#pragma unroll
    for (int nt = 0; nt < 16; nt++) {
        int col = nt * 8 + 2 * t4;
        if (v0) {
            __half2 u = __float22half2_rn(make_float2(acc[nt][0], acc[nt][1]));
            *reinterpret_cast<__half2*>(xw + (size_t)r0 * H + col) = u;
        }
        if (v1) {
            __half2 u = __float22half2_rn(make_float2(acc[nt][2], acc[nt][3]));
            *reinterpret_cast<__half2*>(xw + (size_t)r1 * H + col) = u;
        }
    }
}

// ---------------------------------------------------------------------------
// Pull aggregation: one warp per node; TWO neighbors per warp LDG.128.
// fp16 row = 256B = 16 x uint4. Lanes 0-15 -> neighbor j, lanes 16-31 ->
// neighbor j+1; x2 unroll = 4 neighbors/iter. Cross-half combine: shfl_xor 16.
//   out[d] = relu( dinv[d]*( sum_s dinv[s]*xw[s] + dinv[d]*xw[d] ) + b )
// ---------------------------------------------------------------------------
__global__ void __launch_bounds__(256) gather_kernel(
    const int* __restrict__ csr_src,
    const int* __restrict__ off,
    const float* __restrict__ dinv,
    const __half* __restrict__ xw,
    const float* __restrict__ b,
    float* __restrict__ out, int n)
{
    const int node = (blockIdx.x * blockDim.x + threadIdx.x) >> 5;
    const int lane = threadIdx.x & 31;
    if (node >= n) return;

    const int half = lane >> 4;     // 0 or 1
    const int l16  = lane & 15;     // uint4 index within row

    const uint4* xw4 = reinterpret_cast<const uint4*>(xw);  // 16 per row
    int j = off[node];
    const int end = off[node + 1];

    float accA[8] = {0,0,0,0,0,0,0,0};
    float accB[8] = {0,0,0,0,0,0,0,0};

    // 4 neighbors per iteration: {j+half, j+2+half} across the two halves.
    for (; j + 3 < end; j += 4) {
        int sA = csr_src[j + half];
        int sB = csr_src[j + 2 + half];
        float dA = dinv[sA];
        float dB = dinv[sB];
        uint4 uA = xw4[(size_t)sA * 16 + l16];
        uint4 uB = xw4[(size_t)sB * 16 + l16];

        float2 p;
        p = __half22float2(*reinterpret_cast<__half2*>(&uA.x)); accA[0] += dA*p.x; accA[1] += dA*p.y;
        p = __half22float2(*reinterpret_cast<__half2*>(&uA.y)); accA[2] += dA*p.x; accA[3] += dA*p.y;
        p = __half22float2(*reinterpret_cast<__half2*>(&uA.z)); accA[4] += dA*p.x; accA[5] += dA*p.y;
        p = __half22float2(*reinterpret_cast<__half2*>(&uA.w)); accA[6] += dA*p.x; accA[7] += dA*p.y;
        p = __half22float2(*reinterpret_cast<__half2*>(&uB.x)); accB[0] += dB*p.x; accB[1] += dB*p.y;
        p = __half22float2(*reinterpret_cast<__half2*>(&uB.y)); accB[2] += dB*p.x; accB[3] += dB*p.y;
        p = __half22float2(*reinterpret_cast<__half2*>(&uB.z)); accB[4] += dB*p.x; accB[5] += dB*p.y;
        p = __half22float2(*reinterpret_cast<__half2*>(&uB.w)); accB[6] += dB*p.x; accB[7] += dB*p.y;
    }
    // Remainder (0..3 neighbors), 2 at a time with predication.
    for (; j < end; j += 2) {
        int idx = j + half;
        if (idx < end) {
            int s = csr_src[idx];
            float d = dinv[s];
            uint4 u = xw4[(size_t)s * 16 + l16];
            float2 p;
            p = __half22float2(*reinterpret_cast<__half2*>(&u.x)); accA[0] += d*p.x; accA[1] += d*p.y;
            p = __half22float2(*reinterpret_cast<__half2*>(&u.y)); accA[2] += d*p.x; accA[3] += d*p.y;
            p = __half22float2(*reinterpret_cast<__half2*>(&u.z)); accA[4] += d*p.x; accA[5] += d*p.y;
            p = __half22float2(*reinterpret_cast<__half2*>(&u.w)); accA[6] += d*p.x; accA[7] += d*p.y;
        }
    }

    // Combine the two halves: lane l and l^16 hold the same 8 columns.
    float acc[8];
#pragma unroll
    for (int c = 0; c < 8; c++) {
        float v = accA[c] + accB[c];
        acc[c] = v + __shfl_xor_sync(0xFFFFFFFFu, v, 16);
    }

    // Self loop + bias + relu. Lane (l16, half) covers cols [8*l16+4*half, +4).
    float dd = dinv[node];
    uint4 us = xw4[(size_t)node * 16 + l16];
    float2 s0, s1;
    if (half == 0) {
        s0 = __half22float2(*reinterpret_cast<__half2*>(&us.x));
        s1 = __half22float2(*reinterpret_cast<__half2*>(&us.y));
    } else {
        s0 = __half22float2(*reinterpret_cast<__half2*>(&us.z));
        s1 = __half22float2(*reinterpret_cast<__half2*>(&us.w));
    }
    const int f4 = 2 * l16 + half;                       // float4 index in row
    float4 bb = reinterpret_cast<const float4*>(b)[f4];

    const int base = 4 * half;
    float4 r;
    r.x = fmaxf(dd * (acc[base + 0] + dd * s0.x) + bb.x, 0.f);
    r.y = fmaxf(dd * (acc[base + 1] + dd * s0.y) + bb.y, 0.f);
    r.z = fmaxf(dd * (acc[base + 2] + dd * s1.x) + bb.z, 0.f);
    r.w = fmaxf(dd * (acc[base + 3] + dd * s1.y) + bb.w, 0.f);
    reinterpret_cast<float4*>(out)[(size_t)node * 32 + f4] = r;
}

// ---------------------------------------------------------------------------
// Launch
// ---------------------------------------------------------------------------
extern "C" void kernel_launch(void* const* d_in, const int* in_sizes, int n_in,
                              void* d_out, int out_size)
{
    const float* x  = (const float*)d_in[0];
    const int*   ei = (const int*)d_in[1];
    const float* W1 = (const float*)d_in[2];
    const float* b1 = (const float*)d_in[3];
    const float* W2 = (const float*)d_in[4];
    const float* b2 = (const float*)d_in[5];
    float* out = (float*)d_out;

    const int n = in_sizes[0] / H;       // 50000
    const int e = in_sizes[1] / 2;       // 600000

    float*  dinv;   cudaGetSymbolAddress((void**)&dinv,   g_dinv);
    int*    cnt;    cudaGetSymbolAddress((void**)&cnt,    g_cnt);
    int*    off;    cudaGetSymbolAddress((void**)&off,    g_off);
    int*    cursor; cudaGetSymbolAddress((void**)&cursor, g_cursor);
    int*    csr;    cudaGetSymbolAddress((void**)&csr,    g_csr_src);
    __half* xw;     cudaGetSymbolAddress((void**)&xw,     g_xw);
    float*  h;      cudaGetSymbolAddress((void**)&h,      g_h);

    const int smem_w = 128 * WPAD * sizeof(float);   // 69,632 B
    static int smem_set = 0;
    if (!smem_set) {
        cudaFuncSetAttribute(gemm_tf32_kernel,
                             cudaFuncAttributeMaxDynamicSharedMemorySize, smem_w);
        smem_set = 1;
    }

    const int T = 256;
    const int blocks_n    = (n + T - 1) / T;
    const int blocks_e    = (e + T - 1) / T;
    const int blocks_gemm = (n + 127) / 128;
    const int blocks_gath = (n * 32 + T - 1) / T;

    // CSR build (shared by both layers)
    zero_cnt_kernel<<<blocks_n, T>>>(cnt, n);
    count_kernel<<<blocks_e, T>>>(ei, cnt, e);
    scan_kernel<<<1, SCAN_T>>>(cnt, off, cursor, dinv, n);
    fill_kernel<<<blocks_e, T>>>(ei, cursor, csr, e);

    // layer 1
    gemm_tf32_kernel<<<blocks_gemm, T, smem_w>>>(x, W1, xw, n);
    gather_kernel<<<blocks_gath, T>>>(csr, off, dinv, xw, b1, h, n);

    // layer 2
    gemm_tf32_kernel<<<blocks_gemm, T, smem_w>>>(h, W2, xw, n);
    gather_kernel<<<blocks_gath, T>>>(csr, off, dinv, xw, b2, out, n);
}

// round 10
// speedup vs baseline: 1.0405x; 1.0405x over previous
#include <cuda_runtime.h>
#include <cuda_fp16.h>
#include <cstdint>

// ---------------------------------------------------------------------------
// 2-layer GCN: h = relu(GCN(relu(GCN(x, W1, b1)), W2, b2))
// GCNConv: out = D^{-1/2}(A+I)D^{-1/2} X W + b      (edge_index is int32)
//
// R10: R8 gather (best: fp16 payload, uint2/lane, x2 unroll) +
//      CSR build overlapped with layer-1 GEMM on a forked capture stream.
// ---------------------------------------------------------------------------

#define MAX_N 50000
#define MAX_E 600000
#define H 128
#define SCAN_T 1024
#define WPAD 136

__device__ float  g_dinv[MAX_N];
__device__ int    g_cnt[MAX_N];
__device__ int    g_off[MAX_N + 1];
__device__ int    g_cursor[MAX_N];
__device__ int    g_csr_src[MAX_E];
__device__ __half g_xw[MAX_N * H];
__device__ float  g_h[MAX_N * H];

// ---------------------------------------------------------------------------
// CSR build
// ---------------------------------------------------------------------------
__global__ void zero_cnt_kernel(int* cnt, int n) {
    int i = blockIdx.x * blockDim.x + threadIdx.x;
    if (i < n) cnt[i] = 0;
}

__global__ void count_kernel(const int* __restrict__ ei, int* cnt, int e) {
    int i = blockIdx.x * blockDim.x + threadIdx.x;
    if (i < e) atomicAdd(&cnt[ei[e + i]], 1);
}

__global__ void __launch_bounds__(SCAN_T) scan_kernel(
    const int* __restrict__ cnt, int* __restrict__ off,
    int* __restrict__ cursor, float* __restrict__ dinv, int n)
{
    __shared__ int part[SCAN_T];
    const int t = threadIdx.x;
    const int chunk = (n + SCAN_T - 1) / SCAN_T;
    const int beg = t * chunk;
    const int end = min(beg + chunk, n);

    int local = 0;
    for (int i = beg; i < end; i++) local += cnt[i];
    part[t] = local;
    __syncthreads();

    for (int s = 1; s < SCAN_T; s <<= 1) {
        int v = (t >= s) ? part[t - s] : 0;
        __syncthreads();
        part[t] += v;
        __syncthreads();
    }

    int run = (t == 0) ? 0 : part[t - 1];
    for (int i = beg; i < end; i++) {
        int c = cnt[i];
        off[i] = run;
        cursor[i] = run;
        dinv[i] = rsqrtf(1.0f + (float)c);
        run += c;
    }
    if (t == SCAN_T - 1) off[n] = run;
}

__global__ void fill_kernel(const int* __restrict__ ei,
                            int* __restrict__ cursor,
                            int* __restrict__ csr_src, int e)
{
    int i = blockIdx.x * blockDim.x + threadIdx.x;
    if (i < e) {
        int s = ei[i];
        int d = ei[e + i];
        int p = atomicAdd(&cursor[d], 1);
        csr_src[p] = s;
    }
}

// ---------------------------------------------------------------------------
// tf32 helpers
// ---------------------------------------------------------------------------
__device__ __forceinline__ uint32_t f2tf32(float f) {
    uint32_t r;
    asm("cvt.rna.tf32.f32 %0, %1;" : "=r"(r) : "f"(f));
    return r;
}

__device__ __forceinline__ void mma_tf32(float* c,
    uint32_t a0, uint32_t a1, uint32_t a2, uint32_t a3,
    uint32_t b0, uint32_t b1)
{
    asm volatile(
        "mma.sync.aligned.m16n8k8.row.col.f32.tf32.tf32.f32 "
        "{%0,%1,%2,%3}, {%4,%5,%6,%7}, {%8,%9}, {%0,%1,%2,%3};"
        : "+f"(c[0]), "+f"(c[1]), "+f"(c[2]), "+f"(c[3])
        : "r"(a0), "r"(a1), "r"(a2), "r"(a3), "r"(b0), "r"(b1));
}

// ---------------------------------------------------------------------------
// GEMM (tensor cores, pipelined): xw(fp16) = A(fp32) @ W(fp32 -> tf32).
// Block 256 thr (8 warps) -> 128 rows; warp -> 16 rows x 128 cols.
// Full W staged once in dynamic smem [128][136]; single __syncthreads.
// A fragments double-buffered in registers.
// ---------------------------------------------------------------------------
__global__ void __launch_bounds__(256) gemm_tf32_kernel(
    const float* __restrict__ A, const float* __restrict__ W,
    __half* __restrict__ xw, int n)
{
    extern __shared__ float Ws[];   // [128][WPAD]

    const int tid  = threadIdx.x;
    const int lane = tid & 31;
    const int warp = tid >> 5;
    const int g    = lane >> 2;
    const int t4   = lane & 3;
    const int m0   = blockIdx.x * 128 + warp * 16;

    const float4* W4 = reinterpret_cast<const float4*>(W);
#pragma unroll
    for (int i = tid; i < 128 * 32; i += 256) {
        int r = i >> 5, c4 = i & 31;
        float4 v = W4[r * 32 + c4];
        float* dstp = &Ws[r * WPAD + c4 * 4];
        dstp[0] = __uint_as_float(f2tf32(v.x));
        dstp[1] = __uint_as_float(f2tf32(v.y));
        dstp[2] = __uint_as_float(f2tf32(v.z));
        dstp[3] = __uint_as_float(f2tf32(v.w));
    }

    float acc[16][4];
#pragma unroll
    for (int nt = 0; nt < 16; nt++)
#pragma unroll
        for (int c = 0; c < 4; c++) acc[nt][c] = 0.f;

    const int r0 = m0 + g;
    const int r1 = r0 + 8;
    const bool v0 = r0 < n;
    const bool v1 = r1 < n;
    const float* Ar0 = A + (size_t)r0 * H;
    const float* Ar1 = A + (size_t)r1 * H;

    __syncthreads();

    uint32_t a0 = v0 ? f2tf32(Ar0[t4])     : 0u;
    uint32_t a1 = v1 ? f2tf32(Ar1[t4])     : 0u;
    uint32_t a2 = v0 ? f2tf32(Ar0[t4 + 4]) : 0u;
    uint32_t a3 = v1 ? f2tf32(Ar1[t4 + 4]) : 0u;

#pragma unroll
    for (int kc = 0; kc < 16; kc++) {
        uint32_t na0 = 0u, na1 = 0u, na2 = 0u, na3 = 0u;
        if (kc < 15) {
            const int c0 = (kc + 1) * 8 + t4;
            na0 = v0 ? f2tf32(Ar0[c0])     : 0u;
            na1 = v1 ? f2tf32(Ar1[c0])     : 0u;
            na2 = v0 ? f2tf32(Ar0[c0 + 4]) : 0u;
            na3 = v1 ? f2tf32(Ar1[c0 + 4]) : 0u;
        }

        const float* wb0 = &Ws[(kc * 8 + t4) * WPAD];
        const float* wb1 = &Ws[(kc * 8 + t4 + 4) * WPAD];
#pragma unroll
        for (int nt = 0; nt < 16; nt++) {
            uint32_t b0 = __float_as_uint(wb0[nt * 8 + g]);
            uint32_t b1 = __float_as_uint(wb1[nt * 8 + g]);
            mma_tf32(acc[nt], a0, a1, a2, a3, b0, b1);
        }

        a0 = na0; a1 = na1; a2 = na2; a3 = na3;
    }

#pragma unroll
    for (int nt = 0; nt < 16; nt++) {
        int col = nt * 8 + 2 * t4;
        if (v0) {
            __half2 u = __float22half2_rn(make_float2(acc[nt][0], acc[nt][1]));
            *reinterpret_cast<__half2*>(xw + (size_t)r0 * H + col) = u;
        }
        if (v1) {
            __half2 u = __float22half2_rn(make_float2(acc[nt][2], acc[nt][3]));
            *reinterpret_cast<__half2*>(xw + (size_t)r1 * H + col) = u;
        }
    }
}

// ---------------------------------------------------------------------------
// Pull aggregation (R8 best): one warp per node, fp16 payload, fp32 acc,
// x2 unroll. Lane owns 4 cols (uint2 = 8B); 256B/row fully coalesced.
//   out[d] = relu( dinv[d]*( sum_s dinv[s]*xw[s] + dinv[d]*xw[d] ) + b )
// ---------------------------------------------------------------------------
__global__ void __launch_bounds__(256) gather_kernel(
    const int* __restrict__ csr_src,
    const int* __restrict__ off,
    const float* __restrict__ dinv,
    const __half* __restrict__ xw,
    const float* __restrict__ b,
    float* __restrict__ out, int n)
{
    int node = (blockIdx.x * blockDim.x + threadIdx.x) >> 5;
    int lane = threadIdx.x & 31;
    if (node >= n) return;

    const uint2* xw2 = reinterpret_cast<const uint2*>(xw);  // 4 halves per elt
    int j   = off[node];
    const int end = off[node + 1];

    float4 acc0 = make_float4(0.f, 0.f, 0.f, 0.f);
    float4 acc1 = make_float4(0.f, 0.f, 0.f, 0.f);

    for (; j + 1 < end; j += 2) {
        int s0 = csr_src[j];
        int s1 = csr_src[j + 1];
        float d0 = dinv[s0];
        float d1 = dinv[s1];
        uint2 u0 = xw2[(size_t)s0 * 32 + lane];
        uint2 u1 = xw2[(size_t)s1 * 32 + lane];
        float2 p0 = __half22float2(*reinterpret_cast<__half2*>(&u0.x));
        float2 q0 = __half22float2(*reinterpret_cast<__half2*>(&u0.y));
        float2 p1 = __half22float2(*reinterpret_cast<__half2*>(&u1.x));
        float2 q1 = __half22float2(*reinterpret_cast<__half2*>(&u1.y));
        acc0.x += d0 * p0.x; acc0.y += d0 * p0.y;
        acc0.z += d0 * q0.x; acc0.w += d0 * q0.y;
        acc1.x += d1 * p1.x; acc1.y += d1 * p1.y;
        acc1.z += d1 * q1.x; acc1.w += d1 * q1.y;
    }
    if (j < end) {
        int s0 = csr_src[j];
        float d0 = dinv[s0];
        uint2 u0 = xw2[(size_t)s0 * 32 + lane];
        float2 p0 = __half22float2(*reinterpret_cast<__half2*>(&u0.x));
        float2 q0 = __half22float2(*reinterpret_cast<__half2*>(&u0.y));
        acc0.x += d0 * p0.x; acc0.y += d0 * p0.y;
        acc0.z += d0 * q0.x; acc0.w += d0 * q0.y;
    }

    float dd = dinv[node];
    uint2 us = xw2[(size_t)node * 32 + lane];
    float2 ps = __half22float2(*reinterpret_cast<__half2*>(&us.x));
    float2 qs = __half22float2(*reinterpret_cast<__half2*>(&us.y));
    float4 bb = reinterpret_cast<const float4*>(b)[lane];

    float4 r;
    r.x = fmaxf(dd * (acc0.x + acc1.x + dd * ps.x) + bb.x, 0.f);
    r.y = fmaxf(dd * (acc0.y + acc1.y + dd * ps.y) + bb.y, 0.f);
    r.z = fmaxf(dd * (acc0.z + acc1.z + dd * qs.x) + bb.z, 0.f);
    r.w = fmaxf(dd * (acc0.w + acc1.w + dd * qs.y) + bb.w, 0.f);
    reinterpret_cast<float4*>(out)[(size_t)node * 32 + lane] = r;
}

// ---------------------------------------------------------------------------
// Launch: CSR build (stream 0) overlapped with layer-1 GEMM (stream sB).
// Fork/join via events — graph-capture-legal cross-stream dependencies.
// ---------------------------------------------------------------------------
extern "C" void kernel_launch(void* const* d_in, const int* in_sizes, int n_in,
                              void* d_out, int out_size)
{
    const float* x  = (const float*)d_in[0];
    const int*   ei = (const int*)d_in[1];
    const float* W1 = (const float*)d_in[2];
    const float* b1 = (const float*)d_in[3];
    const float* W2 = (const float*)d_in[4];
    const float* b2 = (const float*)d_in[5];
    float* out = (float*)d_out;

    const int n = in_sizes[0] / H;       // 50000
    const int e = in_sizes[1] / 2;       // 600000

    float*  dinv;   cudaGetSymbolAddress((void**)&dinv,   g_dinv);
    int*    cnt;    cudaGetSymbolAddress((void**)&cnt,    g_cnt);
    int*    off;    cudaGetSymbolAddress((void**)&off,    g_off);
    int*    cursor; cudaGetSymbolAddress((void**)&cursor, g_cursor);
    int*    csr;    cudaGetSymbolAddress((void**)&csr,    g_csr_src);
    __half* xw;     cudaGetSymbolAddress((void**)&xw,     g_xw);
    float*  h;      cudaGetSymbolAddress((void**)&h,      g_h);

    const int smem_w = 128 * WPAD * sizeof(float);   // 69,632 B
    static int init_done = 0;
    static cudaStream_t sB = 0;
    static cudaEvent_t evFork = 0, evJoin = 0;
    if (!init_done) {
        cudaFuncSetAttribute(gemm_tf32_kernel,
                             cudaFuncAttributeMaxDynamicSharedMemorySize, smem_w);
        cudaStreamCreateWithFlags(&sB, cudaStreamNonBlocking);
        cudaEventCreateWithFlags(&evFork, cudaEventDisableTiming);
        cudaEventCreateWithFlags(&evJoin, cudaEventDisableTiming);
        init_done = 1;
    }

    const int T = 256;
    const int blocks_n    = (n + T - 1) / T;
    const int blocks_e    = (e + T - 1) / T;
    const int blocks_gemm = (n + 127) / 128;
    const int blocks_gath = (n * 32 + T - 1) / T;

    // Fork: layer-1 GEMM on sB (depends only on x, W1).
    cudaEventRecord(evFork, (cudaStream_t)0);
    cudaStreamWaitEvent(sB, evFork, 0);
    gemm_tf32_kernel<<<blocks_gemm, T, smem_w, sB>>>(x, W1, xw, n);
    cudaEventRecord(evJoin, sB);

    // CSR build on stream 0 (depends only on ei), concurrent with GEMM-1.
    zero_cnt_kernel<<<blocks_n, T>>>(cnt, n);
    count_kernel<<<blocks_e, T>>>(ei, cnt, e);
    scan_kernel<<<1, SCAN_T>>>(cnt, off, cursor, dinv, n);
    fill_kernel<<<blocks_e, T>>>(ei, cursor, csr, e);

    // Join: gather-1 needs both CSR and xw.
    cudaStreamWaitEvent((cudaStream_t)0, evJoin, 0);
    gather_kernel<<<blocks_gath, T>>>(csr, off, dinv, xw, b1, h, n);

    // layer 2 (serial: gemm2 needs h, gather2 needs xw2)
    gemm_tf32_kernel<<<blocks_gemm, T, smem_w>>>(h, W2, xw, n);
    gather_kernel<<<blocks_gath, T>>>(csr, off, dinv, xw, b2, out, n);
}

// round 11
// speedup vs baseline: 1.8974x; 1.8235x over previous
#include <cuda_runtime.h>
#include <cuda_fp16.h>
#include <cstdint>

// ---------------------------------------------------------------------------
// 2-layer GCN: h = relu(GCN(relu(GCN(x, W1, b1)), W2, b2))
// GCNConv: out = D^{-1/2}(A+I)D^{-1/2} X W + b      (edge_index is int32)
//
// R11: single-block scan replaced with 3-pass full-chip scan (S1/S2/S3).
//      Otherwise identical to R10 (fp16 gather payload, tf32 GEMM, overlap).
// ---------------------------------------------------------------------------

#define MAX_N 50000
#define MAX_E 600000
#define H 128
#define WPAD 136
#define SCAN_BLK 1024          // elements per S1 block (256 thr x 4)
#define MAX_NB ((MAX_N + SCAN_BLK - 1) / SCAN_BLK)

__device__ float  g_dinv[MAX_N];
__device__ int    g_cnt[MAX_N];
__device__ int    g_off[MAX_N + 1];
__device__ int    g_cursor[MAX_N];
__device__ int    g_bsum[MAX_NB + 1];
__device__ int    g_csr_src[MAX_E];
__device__ __half g_xw[MAX_N * H];
__device__ float  g_h[MAX_N * H];

// ---------------------------------------------------------------------------
// CSR build
// ---------------------------------------------------------------------------
__global__ void zero_cnt_kernel(int* cnt, int n) {
    int i = blockIdx.x * blockDim.x + threadIdx.x;
    if (i < n) cnt[i] = 0;
}

__global__ void count_kernel(const int* __restrict__ ei, int* cnt, int e) {
    int i = blockIdx.x * blockDim.x + threadIdx.x;
    if (i < e) atomicAdd(&cnt[ei[e + i]], 1);
}

// S1: per-block scan of SCAN_BLK counts. off[i] <- block-local exclusive
// prefix; bsum[b] <- block total.
__global__ void __launch_bounds__(256) scan1_kernel(
    const int* __restrict__ cnt, int* __restrict__ off,
    int* __restrict__ bsum, int n)
{
    __shared__ int ts[256];
    const int t = threadIdx.x;
    const int base = blockIdx.x * SCAN_BLK + t * 4;

    int c0 = (base + 0 < n) ? cnt[base + 0] : 0;
    int c1 = (base + 1 < n) ? cnt[base + 1] : 0;
    int c2 = (base + 2 < n) ? cnt[base + 2] : 0;
    int c3 = (base + 3 < n) ? cnt[base + 3] : 0;

    ts[t] = c0 + c1 + c2 + c3;
    __syncthreads();
#pragma unroll
    for (int s = 1; s < 256; s <<= 1) {
        int v = (t >= s) ? ts[t - s] : 0;
        __syncthreads();
        ts[t] += v;
        __syncthreads();
    }
    if (t == 255) bsum[blockIdx.x] = ts[255];

    int run = (t == 0) ? 0 : ts[t - 1];
    if (base + 0 < n) off[base + 0] = run;  run += c0;
    if (base + 1 < n) off[base + 1] = run;  run += c1;
    if (base + 2 < n) off[base + 2] = run;  run += c2;
    if (base + 3 < n) off[base + 3] = run;
}

// S2: scan the (<=64) block sums; write exclusive prefixes back; off[n]=total.
__global__ void __launch_bounds__(64) scan2_kernel(
    int* __restrict__ bsum, int* __restrict__ off, int nb, int n)
{
    __shared__ int s[64];
    const int t = threadIdx.x;
    s[t] = (t < nb) ? bsum[t] : 0;
    __syncthreads();
#pragma unroll
    for (int st = 1; st < 64; st <<= 1) {
        int v = (t >= st) ? s[t - st] : 0;
        __syncthreads();
        s[t] += v;
        __syncthreads();
    }
    if (t < nb) bsum[t] = (t == 0) ? 0 : s[t - 1];
    if (t == 63) off[n] = s[63];
}

// S3: add block prefix; set cursor and dinv.
__global__ void scan3_kernel(
    const int* __restrict__ cnt, const int* __restrict__ bsum,
    int* __restrict__ off, int* __restrict__ cursor,
    float* __restrict__ dinv, int n)
{
    int i = blockIdx.x * blockDim.x + threadIdx.x;
    if (i < n) {
        int o = off[i] + bsum[i / SCAN_BLK];
        off[i] = o;
        cursor[i] = o;
        dinv[i] = rsqrtf(1.0f + (float)cnt[i]);
    }
}

__global__ void fill_kernel(const int* __restrict__ ei,
                            int* __restrict__ cursor,
                            int* __restrict__ csr_src, int e)
{
    int i = blockIdx.x * blockDim.x + threadIdx.x;
    if (i < e) {
        int s = ei[i];
        int d = ei[e + i];
        int p = atomicAdd(&cursor[d], 1);
        csr_src[p] = s;
    }
}

// ---------------------------------------------------------------------------
// tf32 helpers
// ---------------------------------------------------------------------------
__device__ __forceinline__ uint32_t f2tf32(float f) {
    uint32_t r;
    asm("cvt.rna.tf32.f32 %0, %1;" : "=r"(r) : "f"(f));
    return r;
}

__device__ __forceinline__ void mma_tf32(float* c,
    uint32_t a0, uint32_t a1, uint32_t a2, uint32_t a3,
    uint32_t b0, uint32_t b1)
{
    asm volatile(
        "mma.sync.aligned.m16n8k8.row.col.f32.tf32.tf32.f32 "
        "{%0,%1,%2,%3}, {%4,%5,%6,%7}, {%8,%9}, {%0,%1,%2,%3};"
        : "+f"(c[0]), "+f"(c[1]), "+f"(c[2]), "+f"(c[3])
        : "r"(a0), "r"(a1), "r"(a2), "r"(a3), "r"(b0), "r"(b1));
}

// ---------------------------------------------------------------------------
// GEMM (tensor cores, pipelined): xw(fp16) = A(fp32) @ W(fp32 -> tf32).
// ---------------------------------------------------------------------------
__global__ void __launch_bounds__(256) gemm_tf32_kernel(
    const float* __restrict__ A, const float* __restrict__ W,
    __half* __restrict__ xw, int n)
{
    extern __shared__ float Ws[];   // [128][WPAD]

    const int tid  = threadIdx.x;
    const int lane = tid & 31;
    const int warp = tid >> 5;
    const int g    = lane >> 2;
    const int t4   = lane & 3;
    const int m0   = blockIdx.x * 128 + warp * 16;

    const float4* W4 = reinterpret_cast<const float4*>(W);
#pragma unroll
    for (int i = tid; i < 128 * 32; i += 256) {
        int r = i >> 5, c4 = i & 31;
        float4 v = W4[r * 32 + c4];
        float* dstp = &Ws[r * WPAD + c4 * 4];
        dstp[0] = __uint_as_float(f2tf32(v.x));
        dstp[1] = __uint_as_float(f2tf32(v.y));
        dstp[2] = __uint_as_float(f2tf32(v.z));
        dstp[3] = __uint_as_float(f2tf32(v.w));
    }

    float acc[16][4];
#pragma unroll
    for (int nt = 0; nt < 16; nt++)
#pragma unroll
        for (int c = 0; c < 4; c++) acc[nt][c] = 0.f;

    const int r0 = m0 + g;
    const int r1 = r0 + 8;
    const bool v0 = r0 < n;
    const bool v1 = r1 < n;
    const float* Ar0 = A + (size_t)r0 * H;
    const float* Ar1 = A + (size_t)r1 * H;

    __syncthreads();

    uint32_t a0 = v0 ? f2tf32(Ar0[t4])     : 0u;
    uint32_t a1 = v1 ? f2tf32(Ar1[t4])     : 0u;
    uint32_t a2 = v0 ? f2tf32(Ar0[t4 + 4]) : 0u;
    uint32_t a3 = v1 ? f2tf32(Ar1[t4 + 4]) : 0u;

#pragma unroll
    for (int kc = 0; kc < 16; kc++) {
        uint32_t na0 = 0u, na1 = 0u, na2 = 0u, na3 = 0u;
        if (kc < 15) {
            const int c0 = (kc + 1) * 8 + t4;
            na0 = v0 ? f2tf32(Ar0[c0])     : 0u;
            na1 = v1 ? f2tf32(Ar1[c0])     : 0u;
            na2 = v0 ? f2tf32(Ar0[c0 + 4]) : 0u;
            na3 = v1 ? f2tf32(Ar1[c0 + 4]) : 0u;
        }

        const float* wb0 = &Ws[(kc * 8 + t4) * WPAD];
        const float* wb1 = &Ws[(kc * 8 + t4 + 4) * WPAD];
#pragma unroll
        for (int nt = 0; nt < 16; nt++) {
            uint32_t b0 = __float_as_uint(wb0[nt * 8 + g]);
            uint32_t b1 = __float_as_uint(wb1[nt * 8 + g]);
            mma_tf32(acc[nt], a0, a1, a2, a3, b0, b1);
        }

        a0 = na0; a1 = na1; a2 = na2; a3 = na3;
    }

#pragma unroll
    for (int nt = 0; nt < 16; nt++) {
        int col = nt * 8 + 2 * t4;
        if (v0) {
            __half2 u = __float22half2_rn(make_float2(acc[nt][0], acc[nt][1]));
            *reinterpret_cast<__half2*>(xw + (size_t)r0 * H + col) = u;
        }
        if (v1) {
            __half2 u = __float22half2_rn(make_float2(acc[nt][2], acc[nt][3]));
            *reinterpret_cast<__half2*>(xw + (size_t)r1 * H + col) = u;
        }
    }
}

// ---------------------------------------------------------------------------
// Pull aggregation (R8 best): one warp per node, fp16 payload, fp32 acc.
// ---------------------------------------------------------------------------
__global__ void __launch_bounds__(256) gather_kernel(
    const int* __restrict__ csr_src,
    const int* __restrict__ off,
    const float* __restrict__ dinv,
    const __half* __restrict__ xw,
    const float* __restrict__ b,
    float* __restrict__ out, int n)
{
    int node = (blockIdx.x * blockDim.x + threadIdx.x) >> 5;
    int lane = threadIdx.x & 31;
    if (node >= n) return;

    const uint2* xw2 = reinterpret_cast<const uint2*>(xw);
    int j   = off[node];
    const int end = off[node + 1];

    float4 acc0 = make_float4(0.f, 0.f, 0.f, 0.f);
    float4 acc1 = make_float4(0.f, 0.f, 0.f, 0.f);

    for (; j + 1 < end; j += 2) {
        int s0 = csr_src[j];
        int s1 = csr_src[j + 1];
        float d0 = dinv[s0];
        float d1 = dinv[s1];
        uint2 u0 = xw2[(size_t)s0 * 32 + lane];
        uint2 u1 = xw2[(size_t)s1 * 32 + lane];
        float2 p0 = __half22float2(*reinterpret_cast<__half2*>(&u0.x));
        float2 q0 = __half22float2(*reinterpret_cast<__half2*>(&u0.y));
        float2 p1 = __half22float2(*reinterpret_cast<__half2*>(&u1.x));
        float2 q1 = __half22float2(*reinterpret_cast<__half2*>(&u1.y));
        acc0.x += d0 * p0.x; acc0.y += d0 * p0.y;
        acc0.z += d0 * q0.x; acc0.w += d0 * q0.y;
        acc1.x += d1 * p1.x; acc1.y += d1 * p1.y;
        acc1.z += d1 * q1.x; acc1.w += d1 * q1.y;
    }
    if (j < end) {
        int s0 = csr_src[j];
        float d0 = dinv[s0];
        uint2 u0 = xw2[(size_t)s0 * 32 + lane];
        float2 p0 = __half22float2(*reinterpret_cast<__half2*>(&u0.x));
        float2 q0 = __half22float2(*reinterpret_cast<__half2*>(&u0.y));
        acc0.x += d0 * p0.x; acc0.y += d0 * p0.y;
        acc0.z += d0 * q0.x; acc0.w += d0 * q0.y;
    }

    float dd = dinv[node];
    uint2 us = xw2[(size_t)node * 32 + lane];
    float2 ps = __half22float2(*reinterpret_cast<__half2*>(&us.x));
    float2 qs = __half22float2(*reinterpret_cast<__half2*>(&us.y));
    float4 bb = reinterpret_cast<const float4*>(b)[lane];

    float4 r;
    r.x = fmaxf(dd * (acc0.x + acc1.x + dd * ps.x) + bb.x, 0.f);
    r.y = fmaxf(dd * (acc0.y + acc1.y + dd * ps.y) + bb.y, 0.f);
    r.z = fmaxf(dd * (acc0.z + acc1.z + dd * qs.x) + bb.z, 0.f);
    r.w = fmaxf(dd * (acc0.w + acc1.w + dd * qs.y) + bb.w, 0.f);
    reinterpret_cast<float4*>(out)[(size_t)node * 32 + lane] = r;
}

// ---------------------------------------------------------------------------
// Launch: CSR build (stream 0) overlapped with layer-1 GEMM (stream sB).
// ---------------------------------------------------------------------------
extern "C" void kernel_launch(void* const* d_in, const int* in_sizes, int n_in,
                              void* d_out, int out_size)
{
    const float* x  = (const float*)d_in[0];
    const int*   ei = (const int*)d_in[1];
    const float* W1 = (const float*)d_in[2];
    const float* b1 = (const float*)d_in[3];
    const float* W2 = (const float*)d_in[4];
    const float* b2 = (const float*)d_in[5];
    float* out = (float*)d_out;

    const int n = in_sizes[0] / H;       // 50000
    const int e = in_sizes[1] / 2;       // 600000

    float*  dinv;   cudaGetSymbolAddress((void**)&dinv,   g_dinv);
    int*    cnt;    cudaGetSymbolAddress((void**)&cnt,    g_cnt);
    int*    off;    cudaGetSymbolAddress((void**)&off,    g_off);
    int*    cursor; cudaGetSymbolAddress((void**)&cursor, g_cursor);
    int*    bsum;   cudaGetSymbolAddress((void**)&bsum,   g_bsum);
    int*    csr;    cudaGetSymbolAddress((void**)&csr,    g_csr_src);
    __half* xw;     cudaGetSymbolAddress((void**)&xw,     g_xw);
    float*  h;      cudaGetSymbolAddress((void**)&h,      g_h);

    const int smem_w = 128 * WPAD * sizeof(float);   // 69,632 B
    static int init_done = 0;
    static cudaStream_t sB = 0;
    static cudaEvent_t evFork = 0, evJoin = 0;
    if (!init_done) {
        cudaFuncSetAttribute(gemm_tf32_kernel,
                             cudaFuncAttributeMaxDynamicSharedMemorySize, smem_w);
        cudaStreamCreateWithFlags(&sB, cudaStreamNonBlocking);
        cudaEventCreateWithFlags(&evFork, cudaEventDisableTiming);
        cudaEventCreateWithFlags(&evJoin, cudaEventDisableTiming);
        init_done = 1;
    }

    const int T = 256;
    const int blocks_n    = (n + T - 1) / T;
    const int blocks_e    = (e + T - 1) / T;
    const int blocks_gemm = (n + 127) / 128;
    const int blocks_gath = (n * 32 + T - 1) / T;
    const int nb          = (n + SCAN_BLK - 1) / SCAN_BLK;   // 49

    // Fork: layer-1 GEMM on sB (depends only on x, W1).
    cudaEventRecord(evFork, (cudaStream_t)0);
    cudaStreamWaitEvent(sB, evFork, 0);
    gemm_tf32_kernel<<<blocks_gemm, T, smem_w, sB>>>(x, W1, xw, n);
    cudaEventRecord(evJoin, sB);

    // CSR build on stream 0 (depends only on ei), concurrent with GEMM-1.
    zero_cnt_kernel<<<blocks_n, T>>>(cnt, n);
    count_kernel<<<blocks_e, T>>>(ei, cnt, e);
    scan1_kernel<<<nb, 256>>>(cnt, off, bsum, n);
    scan2_kernel<<<1, 64>>>(bsum, off, nb, n);
    scan3_kernel<<<blocks_n, T>>>(cnt, bsum, off, cursor, dinv, n);
    fill_kernel<<<blocks_e, T>>>(ei, cursor, csr, e);

    // Join: gather-1 needs both CSR and xw.
    cudaStreamWaitEvent((cudaStream_t)0, evJoin, 0);
    gather_kernel<<<blocks_gath, T>>>(csr, off, dinv, xw, b1, h, n);

    // layer 2
    gemm_tf32_kernel<<<blocks_gemm, T, smem_w>>>(h, W2, xw, n);
    gather_kernel<<<blocks_gath, T>>>(csr, off, dinv, xw, b2, out, n);
}